// round 15
// baseline (speedup 1.0000x reference)
#include <cuda_runtime.h>
#include <stdint.h>
#include <math.h>

// ---------------------------------------------------------------------------
// QunatEncoderBlock: windowed attention + MLP with 8-bit fake quantization.
// Matmuls exact in int8->int32 via mma.sync m16n8k32 (legacy tensor-pipe path
// on sm_103a; tcgen05 blocked by compute_103 PTX target).
// Round 15: GEMM fragment loads via ldmatrix.x4 (48 LDS -> 12 LDSM per k-tile
// per warp). Epilogues/attention/LN unchanged from round 14.
// ---------------------------------------------------------------------------

#define DIMC   768
#define NHEAD  12
#define HDIM   64
#define MLPD   3072
#define WSZ    14
#define NTOK   196
#define NWIN   100
#define BHD    1200
#define PIX    16384
#define HH     64
#define WW     64
#define VPAD   208

// ------------------------------ scratch (device globals) -------------------
__device__ __align__(16) int8_t g_winq [PIX * DIMC];
__device__ __align__(16) int8_t g_wqkv [3 * DIMC * DIMC];
__device__ __align__(16) int8_t g_wproj[DIMC * DIMC];
__device__ __align__(16) int8_t g_wl1  [MLPD * DIMC];
__device__ __align__(16) int8_t g_wl2  [DIMC * MLPD];
__device__ __align__(16) int8_t g_q    [BHD * NTOK * HDIM];
__device__ __align__(16) int8_t g_k    [BHD * NTOK * HDIM];
__device__ __align__(16) int8_t g_vT   [BHD * HDIM * VPAD];
__device__ __align__(16) int8_t g_ov   [PIX * DIMC];
__device__ float  g_xres[(size_t)PIX * DIMC];
__device__ __align__(16) int8_t g_y    [PIX * DIMC];
__device__ __align__(16) int8_t g_hbuf [(size_t)PIX * MLPD];

__device__ __forceinline__ const int8_t* srcA(int id) {
    switch (id) { case 0: return g_winq; case 3: return g_ov;
                  case 4: return g_y;    default: return g_hbuf; }
}
__device__ __forceinline__ const int8_t* srcB(int id) {
    switch (id) { case 0: return g_wqkv; case 3: return g_wproj;
                  case 4: return g_wl1;  default: return g_wl2; }
}

// ------------------------------ helpers ------------------------------------
__device__ __forceinline__ int q8i(float x, float inv) {
    float r = rintf(x * inv);
    return (int)fminf(fmaxf(r, -128.0f), 127.0f);
}
__device__ __forceinline__ int8_t fq8m(float x, float inv) { return (int8_t)q8i(x, inv); }

__device__ __forceinline__ void mma_s8(int& c0, int& c1, int& c2, int& c3,
                                       int a0, int a1, int a2, int a3, int b0, int b1) {
    asm volatile(
        "mma.sync.aligned.m16n8k32.row.col.s32.s8.s8.s32 "
        "{%0,%1,%2,%3}, {%4,%5,%6,%7}, {%8,%9}, {%0,%1,%2,%3};"
        : "+r"(c0), "+r"(c1), "+r"(c2), "+r"(c3)
        : "r"(a0), "r"(a1), "r"(a2), "r"(a3), "r"(b0), "r"(b1));
}

__device__ __forceinline__ void ldsm_x4(int& r0, int& r1, int& r2, int& r3, uint32_t addr) {
    asm volatile("ldmatrix.sync.aligned.m8n8.x4.shared.b16 {%0,%1,%2,%3}, [%4];"
                 : "=r"(r0), "=r"(r1), "=r"(r2), "=r"(r3) : "r"(addr));
}

#define CP_ASYNC16(dst, src) \
    asm volatile("cp.async.cg.shared.global [%0], [%1], 16;" :: "r"(dst), "l"(src))
#define CP_COMMIT() asm volatile("cp.async.commit_group;" ::: "memory")
#define CP_WAIT1()  asm volatile("cp.async.wait_group 1;" ::: "memory")

// ------------------------------ fused weight quantization ------------------
#define QW_N0 442368
#define QW_N1 147456
#define QW_N2 589824
#define QW_TOT (QW_N0 + QW_N1 + QW_N2 + QW_N2)

__global__ void __launch_bounds__(256)
quant_w_all(const float* __restrict__ w0, const float* __restrict__ w1,
            const float* __restrict__ w2, const float* __restrict__ w3,
            const float* __restrict__ ws) {
    int i = blockIdx.x * blockDim.x + threadIdx.x;
    if (i >= QW_TOT) return;
    const float* src; int li; float inv; int8_t* dst;
    if (i < QW_N0)                      { src = w0; li = i;                         inv = 1.0f / ws[0]; dst = g_wqkv; }
    else if (i < QW_N0 + QW_N1)         { src = w1; li = i - QW_N0;                 inv = 1.0f / ws[1]; dst = g_wproj; }
    else if (i < QW_N0 + QW_N1 + QW_N2) { src = w2; li = i - QW_N0 - QW_N1;         inv = 1.0f / ws[2]; dst = g_wl1; }
    else                                { src = w3; li = i - QW_N0 - QW_N1 - QW_N2; inv = 1.0f / ws[3]; dst = g_wl2; }
    float4 v = ((const float4*)src)[li];
    int p = (q8i(v.x, inv) & 255) | ((q8i(v.y, inv) & 255) << 8) |
            ((q8i(v.z, inv) & 255) << 16) | ((q8i(v.w, inv) & 255) << 24);
    ((int*)dst)[li] = p;
}

// ------------------------------ LN kernels (warp per token) ----------------
__device__ __forceinline__ void ln_row(const float* __restrict__ xp,
                                       const float* __restrict__ lw,
                                       const float* __restrict__ lb,
                                       float isc, int8_t* __restrict__ outp,
                                       int lane) {
    const float4* xp4 = (const float4*)xp;
    float4 v[6];
    float s = 0.f;
#pragma unroll
    for (int j = 0; j < 6; ++j) {
        v[j] = xp4[lane + 32 * j];
        s += v[j].x + v[j].y + v[j].z + v[j].w;
    }
#pragma unroll
    for (int o = 16; o > 0; o >>= 1) s += __shfl_xor_sync(~0u, s, o);
    float mu = s * (1.0f / DIMC);
    float sq = 0.f;
#pragma unroll
    for (int j = 0; j < 6; ++j) {
        float a = v[j].x - mu, b = v[j].y - mu, c = v[j].z - mu, d = v[j].w - mu;
        sq += a * a + b * b + c * c + d * d;
    }
#pragma unroll
    for (int o = 16; o > 0; o >>= 1) sq += __shfl_xor_sync(~0u, sq, o);
    float inv = 1.0f / sqrtf(sq * (1.0f / DIMC) + 1e-6f);
    const float4* lw4 = (const float4*)lw;
    const float4* lb4 = (const float4*)lb;
#pragma unroll
    for (int j = 0; j < 6; ++j) {
        float4 w4 = lw4[lane + 32 * j];
        float4 b4 = lb4[lane + 32 * j];
        int p = (q8i((v[j].x - mu) * inv * w4.x + b4.x, isc) & 255)
              | ((q8i((v[j].y - mu) * inv * w4.y + b4.y, isc) & 255) << 8)
              | ((q8i((v[j].z - mu) * inv * w4.z + b4.z, isc) & 255) << 16)
              | ((q8i((v[j].w - mu) * inv * w4.w + b4.w, isc) & 255) << 24);
        ((int*)outp)[lane + 32 * j] = p;
    }
}

__global__ void __launch_bounds__(256)
ln1_kernel(const float* __restrict__ x, const float* __restrict__ lw,
           const float* __restrict__ lb, const float* __restrict__ as) {
    int lane = threadIdx.x & 31, wid = threadIdx.x >> 5;
    int m = blockIdx.x * 8 + wid;
    ln_row(x + (size_t)m * DIMC, lw, lb, 1.0f / as[4], g_winq + (size_t)m * DIMC, lane);
}

__global__ void __launch_bounds__(256)
ln2_kernel(const float* __restrict__ lw, const float* __restrict__ lb,
           const float* __restrict__ as) {
    int lane = threadIdx.x & 31, wid = threadIdx.x >> 5;
    int m = blockIdx.x * 8 + wid;
    ln_row(g_xres + (size_t)m * DIMC, lw, lb, 1.0f / as[6], g_y + (size_t)m * DIMC, lane);
}

// ------------------------------ pad-token q/k/vT fill ----------------------
__global__ void __launch_bounds__(256)
pad_qkv_kernel(const float* __restrict__ qb, const float* __restrict__ as) {
    int wi = blockIdx.x;
    int rem = wi % 25, wr = rem / 5, wc = rem % 5;
    if (wr < 4 && wc < 4) return;
    __shared__ int sq[192], sk[192];
    __shared__ int8_t sv[768];
    int tid = threadIdx.x;
    float inv0 = 1.0f / as[0], inv1 = 1.0f / as[1], inv2 = 1.0f / as[2];
    for (int i = tid; i < 192; i += 256) {
        int n = i * 4;
        sq[i] = (q8i(qb[n], inv0) & 255) | ((q8i(qb[n+1], inv0) & 255) << 8)
              | ((q8i(qb[n+2], inv0) & 255) << 16) | ((q8i(qb[n+3], inv0) & 255) << 24);
        sk[i] = (q8i(qb[768+n], inv1) & 255) | ((q8i(qb[768+n+1], inv1) & 255) << 8)
              | ((q8i(qb[768+n+2], inv1) & 255) << 16) | ((q8i(qb[768+n+3], inv1) & 255) << 24);
    }
    for (int i = tid; i < 768; i += 256) sv[i] = fq8m(qb[1536 + i], inv2);
    __syncthreads();
    int lane = tid & 31, w = tid >> 5;
    for (int t = w; t < NTOK; t += 8) {
        int lr = t / WSZ, lc = t % WSZ;
        bool pad = (wr == 4 && lr >= 8) || (wc == 4 && lc >= 8);
        if (!pad) continue;
        for (int i = lane; i < 192; i += 32) {
            int head = i >> 4, di = i & 15;
            ((int*)(g_q + ((size_t)(wi * NHEAD + head) * NTOK + t) * HDIM))[di] = sq[i];
            ((int*)(g_k + ((size_t)(wi * NHEAD + head) * NTOK + t) * HDIM))[di] = sk[i];
        }
        for (int i = lane; i < 768; i += 32) {
            int head = i >> 6, d = i & 63;
            g_vT[((size_t)(wi * NHEAD + head) * HDIM + d) * VPAD + t] = sv[i];
        }
    }
}

// ------------------------------ fused attention (+rel-pos bias) -------------
#define QSTR  20
#define SSTR  60
#define SQ_OFF   0
#define SK_OFF   (208 * QSTR)
#define SV_OFF   (SK_OFF + 200 * QSTR)
#define SS_OFF   (SV_OFF + 64 * SSTR)
#define RH_OFF   (SS_OFF + 208 * SSTR)
#define RW_OFF   (RH_OFF + 64 * 28)
#define REL_OFF  (RW_OFF + 64 * 28)
#define ATT_SMEM ((REL_OFF + 208 * 28) * 4)

__global__ void __launch_bounds__(416)
attn_fused_kernel(const float* __restrict__ rph, const float* __restrict__ rpw,
                  const float* __restrict__ as) {
    extern __shared__ int sm[];
    int* sQ = sm + SQ_OFF; int* sK = sm + SK_OFF;
    int* sVT = sm + SV_OFF; int* sS = sm + SS_OFF;
    float* sRhT = (float*)(sm + RH_OFF);
    float* sRwT = (float*)(sm + RW_OFF);
    float* sRel = (float*)(sm + REL_OFF);
    int bh = blockIdx.x, tid = threadIdx.x;
    int lane = tid & 31, wid = tid >> 5;
    int lrow = lane >> 2, lk = lane & 3;

    const int8_t* qg = g_q  + (size_t)bh * NTOK * HDIM;
    const int8_t* kg = g_k  + (size_t)bh * NTOK * HDIM;
    const int8_t* vg = g_vT + (size_t)bh * HDIM * VPAD;
    for (int idx = tid; idx < 208 * 4; idx += 416) {
        int row = idx >> 2, slot = idx & 3;
        int4 v = make_int4(0, 0, 0, 0);
        if (row < NTOK) v = *(const int4*)(qg + row * HDIM + slot * 16);
        *(int4*)&sQ[row * QSTR + slot * 4] = v;
    }
    for (int idx = tid; idx < 200 * 4; idx += 416) {
        int row = idx >> 2, slot = idx & 3;
        int4 v = make_int4(0, 0, 0, 0);
        if (row < NTOK) v = *(const int4*)(kg + row * HDIM + slot * 16);
        *(int4*)&sK[row * QSTR + slot * 4] = v;
    }
    for (int idx = tid; idx < 64 * 13; idx += 416) {
        int row = idx / 13, slot = idx % 13;
        *(int4*)&sVT[row * SSTR + slot * 4] = *(const int4*)(vg + row * VPAD + slot * 16);
    }
    for (int idx = tid; idx < 208 * 6; idx += 416)
        sS[(idx / 6) * SSTR + 50 + (idx % 6)] = 0;
    for (int i = tid; i < 27 * 64; i += 416) {
        int r = i >> 6, c = i & 63;
        sRhT[c * 28 + r] = rph[i];
        sRwT[c * 28 + r] = rpw[i];
    }
    __syncthreads();

    float a0s = as[0];
    if (tid < NTOK) {
        int t = tid;
        int hh = t / WSZ, ww2 = t % WSZ;
        float ah[WSZ], aw[WSZ];
#pragma unroll
        for (int kk = 0; kk < WSZ; ++kk) { ah[kk] = 0.f; aw[kk] = 0.f; }
#pragma unroll
        for (int j = 0; j < 16; ++j) {
            int packed = sQ[t * QSTR + j];
#pragma unroll
            for (int b = 0; b < 4; ++b) {
                int c = j * 4 + b;
                float qv = (float)((packed << (24 - 8 * b)) >> 24);
                const float* ph = &sRhT[c * 28 + hh + 13];
                const float* pw = &sRwT[c * 28 + ww2 + 13];
#pragma unroll
                for (int kk = 0; kk < WSZ; ++kk) {
                    ah[kk] += qv * ph[-kk];
                    aw[kk] += qv * pw[-kk];
                }
            }
        }
#pragma unroll
        for (int kk = 0; kk < WSZ; ++kk) {
            sRel[t * 28 + kk]      = ah[kk] * a0s;
            sRel[t * 28 + 14 + kk] = aw[kk] * a0s;
        }
    }
    __syncthreads();

    float c_qk = 0.125f * a0s * as[1];
    float inva3 = 1.0f / as[3];
    float c_av = as[3] * as[2];
    float inva5 = 1.0f / as[5];
    int wi = bh / NHEAD, head = bh % NHEAD;
    int wrem = wi % 25, wb = wi / 25, wwr = wrem / 5, wwc = wrem % 5;
    char* sSb = (char*)sS;

    {
        int s = wid;
        int m_lo = s * 16 + lrow, m_hi = m_lo + 8;
        int acc[25][4];
#pragma unroll
        for (int t = 0; t < 25; ++t) { acc[t][0]=acc[t][1]=acc[t][2]=acc[t][3]=0; }
#pragma unroll
        for (int kc = 0; kc < 2; ++kc) {
            int kb = kc * 8;
            int a0 = sQ[m_lo * QSTR + kb + lk];
            int a1 = sQ[m_hi * QSTR + kb + lk];
            int a2 = sQ[m_lo * QSTR + kb + 4 + lk];
            int a3 = sQ[m_hi * QSTR + kb + 4 + lk];
#pragma unroll
            for (int t = 0; t < 25; ++t) {
                int col = t * 8 + lrow;
                mma_s8(acc[t][0], acc[t][1], acc[t][2], acc[t][3],
                       a0, a1, a2, a3, sK[col * QSTR + kb + lk], sK[col * QSTR + kb + 4 + lk]);
            }
        }
        bool vlo = (m_lo < NTOK), vhi = (m_hi < NTOK);
        const float* rlo_p = &sRel[m_lo * 28];
        const float* rhi_p = &sRel[m_hi * 28];
#pragma unroll
        for (int t = 0; t < 25; ++t) {
#pragma unroll
            for (int r = 0; r < 4; ++r) {
                int n = t * 8 + lk * 2 + (r & 1);
                bool vm = (r < 2) ? vlo : vhi;
                float f;
                if (n < NTOK && vm) {
                    const float* rp = (r < 2) ? rlo_p : rhi_p;
                    f = (float)acc[t][r] * c_qk + rp[n / WSZ] + rp[14 + n % WSZ];
                } else f = -1e30f;
                acc[t][r] = __float_as_int(f);
            }
        }
        float mx0 = -1e30f, mx1 = -1e30f;
#pragma unroll
        for (int t = 0; t < 25; ++t) {
            mx0 = fmaxf(mx0, fmaxf(__int_as_float(acc[t][0]), __int_as_float(acc[t][1])));
            mx1 = fmaxf(mx1, fmaxf(__int_as_float(acc[t][2]), __int_as_float(acc[t][3])));
        }
        mx0 = fmaxf(mx0, __shfl_xor_sync(~0u, mx0, 1)); mx0 = fmaxf(mx0, __shfl_xor_sync(~0u, mx0, 2));
        mx1 = fmaxf(mx1, __shfl_xor_sync(~0u, mx1, 1)); mx1 = fmaxf(mx1, __shfl_xor_sync(~0u, mx1, 2));
        float s0 = 0.f, s1 = 0.f;
#pragma unroll
        for (int t = 0; t < 25; ++t) {
            float e0 = __expf(__int_as_float(acc[t][0]) - mx0);
            float e1 = __expf(__int_as_float(acc[t][1]) - mx0);
            float e2 = __expf(__int_as_float(acc[t][2]) - mx1);
            float e3 = __expf(__int_as_float(acc[t][3]) - mx1);
            acc[t][0] = __float_as_int(e0); acc[t][1] = __float_as_int(e1);
            acc[t][2] = __float_as_int(e2); acc[t][3] = __float_as_int(e3);
            s0 += e0 + e1; s1 += e2 + e3;
        }
        s0 += __shfl_xor_sync(~0u, s0, 1); s0 += __shfl_xor_sync(~0u, s0, 2);
        s1 += __shfl_xor_sync(~0u, s1, 1); s1 += __shfl_xor_sync(~0u, s1, 2);
        float r0 = inva3 / s0, r1 = inva3 / s1;
#pragma unroll
        for (int t = 0; t < 25; ++t) {
            int v00 = q8i(__int_as_float(acc[t][0]), r0);
            int v01 = q8i(__int_as_float(acc[t][1]), r0);
            int v10 = q8i(__int_as_float(acc[t][2]), r1);
            int v11 = q8i(__int_as_float(acc[t][3]), r1);
            *(unsigned short*)(sSb + m_lo * (SSTR * 4) + t * 8 + lk * 2) =
                (unsigned short)((v00 & 0xFF) | ((v01 & 0xFF) << 8));
            *(unsigned short*)(sSb + m_hi * (SSTR * 4) + t * 8 + lk * 2) =
                (unsigned short)((v10 & 0xFF) | ((v11 & 0xFF) << 8));
        }
        __syncwarp();
        int oacc[8][4];
#pragma unroll
        for (int j = 0; j < 8; ++j) { oacc[j][0]=oacc[j][1]=oacc[j][2]=oacc[j][3]=0; }
#pragma unroll
        for (int kc = 0; kc < 7; ++kc) {
            int kb = kc * 8;
            int a0 = sS[m_lo * SSTR + kb + lk];
            int a1 = sS[m_hi * SSTR + kb + lk];
            int a2 = sS[m_lo * SSTR + kb + 4 + lk];
            int a3 = sS[m_hi * SSTR + kb + 4 + lk];
#pragma unroll
            for (int j = 0; j < 8; ++j) {
                int col = j * 8 + lrow;
                mma_s8(oacc[j][0], oacc[j][1], oacc[j][2], oacc[j][3],
                       a0, a1, a2, a3, sVT[col * SSTR + kb + lk], sVT[col * SSTR + kb + 4 + lk]);
            }
        }
        int rlo = wwr * WSZ + m_lo / WSZ, clo = wwc * WSZ + m_lo % WSZ;
        int rhi = wwr * WSZ + m_hi / WSZ, chi = wwc * WSZ + m_hi % WSZ;
        bool oklo = vlo && rlo < HH && clo < WW;
        bool okhi = vhi && rhi < HH && chi < WW;
        size_t plo = (((size_t)(wb * HH + rlo)) * WW + clo) * DIMC + head * HDIM;
        size_t phi = (((size_t)(wb * HH + rhi)) * WW + chi) * DIMC + head * HDIM;
#pragma unroll
        for (int j = 0; j < 8; ++j) {
            int n = j * 8 + lk * 2;
            if (oklo) {
                int v0 = q8i((float)oacc[j][0] * c_av, inva5);
                int v1 = q8i((float)oacc[j][1] * c_av, inva5);
                *(unsigned short*)(g_ov + plo + n) =
                    (unsigned short)((v0 & 0xFF) | ((v1 & 0xFF) << 8));
            }
            if (okhi) {
                int v0 = q8i((float)oacc[j][2] * c_av, inva5);
                int v1 = q8i((float)oacc[j][3] * c_av, inva5);
                *(unsigned short*)(g_ov + phi + n) =
                    (unsigned short)((v0 & 0xFF) | ((v1 & 0xFF) << 8));
            }
        }
    }
}

// ------------------------------ int8 IMMA GEMM (cp.async + ldmatrix) --------
// 3 stages x (A 128x80B + B 128x80B) = 61440 bytes; wait_group 1.
// Fragments loaded via ldmatrix.x4 (row stride 80B -> conflict-free LDSM).
#define GEMM_SMEM 61440

template <typename Epi>
__global__ void __launch_bounds__(256)
gemm_i8(int aid, int bid, int Kints, Epi epi) {
    extern __shared__ int gsm[];
    const int8_t* Ab = srcA(aid);
    const int8_t* Bb = srcB(bid);
    int bm = blockIdx.y * 128, bn = blockIdx.x * 128;
    int tid = threadIdx.x;
    int lane = tid & 31, wid = tid >> 5;
    int wm = wid >> 2, wn = wid & 3;
    int lrow = lane >> 2, lk = lane & 3;
    int srow = tid >> 2;
    int slot = tid & 3;

    uint32_t sbase = (uint32_t)__cvta_generic_to_shared(gsm);
    const int* Abase = (const int*)Ab + (size_t)(bm + srow) * Kints + slot * 4;
    const int* Bbase = (const int*)Bb + (size_t)(bn + srow) * Kints + slot * 4;
    size_t rowskip = (size_t)64 * Kints;
    uint32_t a_off = sbase + srow * 80 + slot * 16;
    uint32_t b_off = sbase + 30720 + srow * 80 + slot * 16;

    // ldmatrix per-lane base addresses
    uint32_t aLm = sbase + (wm * 64 + (lane & 15)) * 80 + ((lane >> 4) << 4);
    uint32_t bLm = sbase + 30720 +
                   (wn * 32 + ((lane >> 4) << 3) + (lane & 7)) * 80 +
                   (((lane >> 3) & 1) << 4);

    int acc[4][4][4];
#pragma unroll
    for (int i = 0; i < 4; ++i)
#pragma unroll
        for (int j = 0; j < 4; ++j)
#pragma unroll
            for (int r = 0; r < 4; ++r) acc[i][j][r] = 0;

    auto load_tile = [&](int kt, int stg) {
        int k0 = kt * 16;
        const int* ga = Abase + k0;
        const int* gb = Bbase + k0;
        uint32_t ao = a_off + stg * 10240;
        uint32_t bo = b_off + stg * 10240;
        CP_ASYNC16(ao, ga);
        CP_ASYNC16(ao + 64 * 80, ga + rowskip);
        CP_ASYNC16(bo, gb);
        CP_ASYNC16(bo + 64 * 80, gb + rowskip);
        CP_COMMIT();
    };

    int nk = Kints >> 4;
    load_tile(0, 0);
    load_tile(1, 1);

    for (int kt = 0; kt < nk; ++kt) {
        CP_WAIT1();
        __syncthreads();
        int cur = kt - (kt / 3) * 3;
        uint32_t aC = aLm + cur * 10240;
        uint32_t bC = bLm + cur * 10240;
#pragma unroll
        for (int kc = 0; kc < 2; ++kc) {
            uint32_t koff = kc * 32;
            int b0[4], b1[4];
            ldsm_x4(b0[0], b1[0], b0[1], b1[1], bC + koff);
            ldsm_x4(b0[2], b1[2], b0[3], b1[3], bC + 1280 + koff);
#pragma unroll
            for (int i = 0; i < 4; ++i) {
                int a0, a1, a2, a3;
                ldsm_x4(a0, a1, a2, a3, aC + i * 1280 + koff);
#pragma unroll
                for (int j = 0; j < 4; ++j)
                    mma_s8(acc[i][j][0], acc[i][j][1], acc[i][j][2], acc[i][j][3],
                           a0, a1, a2, a3, b0[j], b1[j]);
            }
        }
        if (kt + 2 < nk) {
            int stg = kt + 2;
            stg -= (stg / 3) * 3;
            load_tile(kt + 2, stg);
        }
    }

    epi.prep();
#pragma unroll
    for (int i = 0; i < 4; ++i) {
        int m0 = bm + wm * 64 + i * 16 + lrow;
#pragma unroll
        for (int j = 0; j < 4; ++j) {
            int n0 = bn + wn * 32 + j * 8 + lk * 2;
            epi.pair(acc[i][j][0], acc[i][j][1], m0, n0);
            epi.pair(acc[i][j][2], acc[i][j][3], m0 + 8, n0);
        }
    }
}

// ------------------------------ GEMM epilogues (paired, n even) -------------
struct EpiQKV {
    const float* as; const float* ws; const float* qb;
    float s1, inv0, inv1, inv2;
    __device__ void prep() {
        s1 = as[4] * ws[0];
        inv0 = 1.0f / as[0]; inv1 = 1.0f / as[1]; inv2 = 1.0f / as[2];
    }
    __device__ void pair(int acc0, int acc1, int m, int n) const {
        float f0 = (float)acc0 * s1 + qb[n];
        float f1 = (float)acc1 * s1 + qb[n + 1];
        int qi = (n >= 1536) ? 2 : (n >= 768 ? 1 : 0);
        int rem = n - qi * 768;
        int head = rem >> 6, d = rem & 63;
        int b = m >> 12, r = (m >> 6) & 63, c = m & 63;
        int wr = r / WSZ, lr = r - wr * WSZ;
        int wc = c / WSZ, lc = c - wc * WSZ;
        int wi = b * 25 + wr * 5 + wc;
        int t = lr * WSZ + lc;
        int bh = wi * NHEAD + head;
        if (qi == 0) {
            int v0 = q8i(f0, inv0), v1 = q8i(f1, inv0);
            *(unsigned short*)(g_q + ((size_t)bh * NTOK + t) * HDIM + d) =
                (unsigned short)((v0 & 0xFF) | ((v1 & 0xFF) << 8));
        } else if (qi == 1) {
            int v0 = q8i(f0, inv1), v1 = q8i(f1, inv1);
            *(unsigned short*)(g_k + ((size_t)bh * NTOK + t) * HDIM + d) =
                (unsigned short)((v0 & 0xFF) | ((v1 & 0xFF) << 8));
        } else {
            g_vT[((size_t)bh * HDIM + d)     * VPAD + t] = fq8m(f0, inv2);
            g_vT[((size_t)bh * HDIM + d + 1) * VPAD + t] = fq8m(f1, inv2);
        }
    }
};
struct EpiProj {
    const float* as; const float* ws; const float* pb; const float* x;
    float s1;
    __device__ void prep() { s1 = as[5] * ws[1]; }
    __device__ void pair(int acc0, int acc1, int m, int n) const {
        size_t idx = (size_t)m * DIMC + n;
        float2 xv = *(const float2*)(x + idx);
        float2 o;
        o.x = xv.x + (float)acc0 * s1 + pb[n];
        o.y = xv.y + (float)acc1 * s1 + pb[n + 1];
        *(float2*)(g_xres + idx) = o;
    }
};
struct EpiL1 {
    const float* as; const float* ws; const float* lb;
    float s1, inv7;
    __device__ void prep() { s1 = as[6] * ws[2]; inv7 = 1.0f / as[7]; }
    __device__ float gelu(float f) const {
        float xx = f * 0.70710678118654752f;
        float ax = fabsf(xx);
        float t = __fdividef(1.0f, 1.0f + 0.3275911f * ax);
        float poly = t * (0.254829592f + t * (-0.284496736f + t * (1.421413741f +
                     t * (-1.453152027f + t * 1.061405429f))));
        float erfv = 1.0f - poly * __expf(-xx * xx);
        erfv = copysignf(erfv, xx);
        return 0.5f * f * (1.0f + erfv);
    }
    __device__ void pair(int acc0, int acc1, int m, int n) const {
        float f0 = (float)acc0 * s1 + lb[n];
        float f1 = (float)acc1 * s1 + lb[n + 1];
        int v0 = q8i(gelu(f0), inv7);
        int v1 = q8i(gelu(f1), inv7);
        *(unsigned short*)(g_hbuf + (size_t)m * MLPD + n) =
            (unsigned short)((v0 & 0xFF) | ((v1 & 0xFF) << 8));
    }
};
struct EpiL2 {
    const float* as; const float* ws; const float* lb; float* out;
    float s1;
    __device__ void prep() { s1 = as[7] * ws[3]; }
    __device__ void pair(int acc0, int acc1, int m, int n) const {
        size_t idx = (size_t)m * DIMC + n;
        float2 rv = *(const float2*)(g_xres + idx);
        float2 o;
        o.x = rv.x + (float)acc0 * s1 + lb[n];
        o.y = rv.y + (float)acc1 * s1 + lb[n + 1];
        *(float2*)(out + idx) = o;
    }
};

// ------------------------------ launch --------------------------------------
extern "C" void kernel_launch(void* const* d_in, const int* in_sizes, int n_in,
                              void* d_out, int out_size) {
    const float* x      = (const float*)d_in[0];
    const float* ln1_w  = (const float*)d_in[1];
    const float* ln1_b  = (const float*)d_in[2];
    const float* ln2_w  = (const float*)d_in[3];
    const float* ln2_b  = (const float*)d_in[4];
    const float* qkv_w  = (const float*)d_in[5];
    const float* qkv_b  = (const float*)d_in[6];
    const float* proj_w = (const float*)d_in[7];
    const float* proj_b = (const float*)d_in[8];
    const float* lin1_w = (const float*)d_in[9];
    const float* lin1_b = (const float*)d_in[10];
    const float* lin2_w = (const float*)d_in[11];
    const float* lin2_b = (const float*)d_in[12];
    const float* rph    = (const float*)d_in[13];
    const float* rpw    = (const float*)d_in[14];
    const float* asc    = (const float*)d_in[15];
    const float* wsc    = (const float*)d_in[16];
    float* out = (float*)d_out;

    cudaFuncSetAttribute(attn_fused_kernel, cudaFuncAttributeMaxDynamicSharedMemorySize, ATT_SMEM);
    cudaFuncSetAttribute(gemm_i8<EpiQKV>,  cudaFuncAttributeMaxDynamicSharedMemorySize, GEMM_SMEM);
    cudaFuncSetAttribute(gemm_i8<EpiProj>, cudaFuncAttributeMaxDynamicSharedMemorySize, GEMM_SMEM);
    cudaFuncSetAttribute(gemm_i8<EpiL1>,   cudaFuncAttributeMaxDynamicSharedMemorySize, GEMM_SMEM);
    cudaFuncSetAttribute(gemm_i8<EpiL2>,   cudaFuncAttributeMaxDynamicSharedMemorySize, GEMM_SMEM);

    quant_w_all<<<(QW_TOT + 255) / 256, 256>>>(qkv_w, proj_w, lin1_w, lin2_w, wsc);

    ln1_kernel<<<PIX / 8, 256>>>(x, ln1_w, ln1_b, asc);
    pad_qkv_kernel<<<NWIN, 256>>>(qkv_b, asc);

    gemm_i8<EpiQKV><<<dim3(18, 128), 256, GEMM_SMEM>>>(0, 0, DIMC / 4,
                                                       EpiQKV{asc, wsc, qkv_b});

    attn_fused_kernel<<<BHD, 416, ATT_SMEM>>>(rph, rpw, asc);

    gemm_i8<EpiProj><<<dim3(6, 128), 256, GEMM_SMEM>>>(3, 3, DIMC / 4,
                                                       EpiProj{asc, wsc, proj_b, x});

    ln2_kernel<<<PIX / 8, 256>>>(ln2_w, ln2_b, asc);

    gemm_i8<EpiL1><<<dim3(24, 128), 256, GEMM_SMEM>>>(4, 4, DIMC / 4,
                                                      EpiL1{asc, wsc, lin1_b});
    gemm_i8<EpiL2><<<dim3(6, 128), 256, GEMM_SMEM>>>(5, 5, MLPD / 4,
                                                     EpiL2{asc, wsc, lin2_b, out});
}

// round 16
// speedup vs baseline: 1.0055x; 1.0055x over previous
#include <cuda_runtime.h>
#include <stdint.h>
#include <math.h>

// ---------------------------------------------------------------------------
// QunatEncoderBlock: windowed attention + MLP with 8-bit fake quantization.
// Matmuls exact in int8->int32 via mma.sync m16n8k32 (legacy tensor-pipe path
// on sm_103a, ~88% achieved; tcgen05 blocked by compute_103 PTX target).
// Round 16: (1) proj/L2 GEMMs use 128x64 tiles (NJ=2) to cut wave-tail waste;
// (2) ln1 + weight-quant + pad-fill merged into one heterogeneous launch.
// GEMM mainloop otherwise identical to measured-best round-15 body.
// ---------------------------------------------------------------------------

#define DIMC   768
#define NHEAD  12
#define HDIM   64
#define MLPD   3072
#define WSZ    14
#define NTOK   196
#define NWIN   100
#define BHD    1200
#define PIX    16384
#define HH     64
#define WW     64
#define VPAD   208

// ------------------------------ scratch (device globals) -------------------
__device__ __align__(16) int8_t g_winq [PIX * DIMC];
__device__ __align__(16) int8_t g_wqkv [3 * DIMC * DIMC];
__device__ __align__(16) int8_t g_wproj[DIMC * DIMC];
__device__ __align__(16) int8_t g_wl1  [MLPD * DIMC];
__device__ __align__(16) int8_t g_wl2  [DIMC * MLPD];
__device__ __align__(16) int8_t g_q    [BHD * NTOK * HDIM];
__device__ __align__(16) int8_t g_k    [BHD * NTOK * HDIM];
__device__ __align__(16) int8_t g_vT   [BHD * HDIM * VPAD];
__device__ __align__(16) int8_t g_ov   [PIX * DIMC];
__device__ float  g_xres[(size_t)PIX * DIMC];
__device__ __align__(16) int8_t g_y    [PIX * DIMC];
__device__ __align__(16) int8_t g_hbuf [(size_t)PIX * MLPD];

__device__ __forceinline__ const int8_t* srcA(int id) {
    switch (id) { case 0: return g_winq; case 3: return g_ov;
                  case 4: return g_y;    default: return g_hbuf; }
}
__device__ __forceinline__ const int8_t* srcB(int id) {
    switch (id) { case 0: return g_wqkv; case 3: return g_wproj;
                  case 4: return g_wl1;  default: return g_wl2; }
}

// ------------------------------ helpers ------------------------------------
__device__ __forceinline__ int q8i(float x, float inv) {
    float r = rintf(x * inv);
    return (int)fminf(fmaxf(r, -128.0f), 127.0f);
}
__device__ __forceinline__ int8_t fq8m(float x, float inv) { return (int8_t)q8i(x, inv); }

__device__ __forceinline__ void mma_s8(int& c0, int& c1, int& c2, int& c3,
                                       int a0, int a1, int a2, int a3, int b0, int b1) {
    asm volatile(
        "mma.sync.aligned.m16n8k32.row.col.s32.s8.s8.s32 "
        "{%0,%1,%2,%3}, {%4,%5,%6,%7}, {%8,%9}, {%0,%1,%2,%3};"
        : "+r"(c0), "+r"(c1), "+r"(c2), "+r"(c3)
        : "r"(a0), "r"(a1), "r"(a2), "r"(a3), "r"(b0), "r"(b1));
}

__device__ __forceinline__ void ldsm_x4(int& r0, int& r1, int& r2, int& r3, uint32_t addr) {
    asm volatile("ldmatrix.sync.aligned.m8n8.x4.shared.b16 {%0,%1,%2,%3}, [%4];"
                 : "=r"(r0), "=r"(r1), "=r"(r2), "=r"(r3) : "r"(addr));
}

#define CP_ASYNC16(dst, src) \
    asm volatile("cp.async.cg.shared.global [%0], [%1], 16;" :: "r"(dst), "l"(src))
#define CP_COMMIT() asm volatile("cp.async.commit_group;" ::: "memory")
#define CP_WAIT1()  asm volatile("cp.async.wait_group 1;" ::: "memory")

// ------------------------------ LN row helper (warp-wide) ------------------
__device__ __forceinline__ void ln_row(const float* __restrict__ xp,
                                       const float* __restrict__ lw,
                                       const float* __restrict__ lb,
                                       float isc, int8_t* __restrict__ outp,
                                       int lane) {
    const float4* xp4 = (const float4*)xp;
    float4 v[6];
    float s = 0.f;
#pragma unroll
    for (int j = 0; j < 6; ++j) {
        v[j] = xp4[lane + 32 * j];
        s += v[j].x + v[j].y + v[j].z + v[j].w;
    }
#pragma unroll
    for (int o = 16; o > 0; o >>= 1) s += __shfl_xor_sync(~0u, s, o);
    float mu = s * (1.0f / DIMC);
    float sq = 0.f;
#pragma unroll
    for (int j = 0; j < 6; ++j) {
        float a = v[j].x - mu, b = v[j].y - mu, c = v[j].z - mu, d = v[j].w - mu;
        sq += a * a + b * b + c * c + d * d;
    }
#pragma unroll
    for (int o = 16; o > 0; o >>= 1) sq += __shfl_xor_sync(~0u, sq, o);
    float inv = 1.0f / sqrtf(sq * (1.0f / DIMC) + 1e-6f);
    const float4* lw4 = (const float4*)lw;
    const float4* lb4 = (const float4*)lb;
#pragma unroll
    for (int j = 0; j < 6; ++j) {
        float4 w4 = lw4[lane + 32 * j];
        float4 b4 = lb4[lane + 32 * j];
        int p = (q8i((v[j].x - mu) * inv * w4.x + b4.x, isc) & 255)
              | ((q8i((v[j].y - mu) * inv * w4.y + b4.y, isc) & 255) << 8)
              | ((q8i((v[j].z - mu) * inv * w4.z + b4.z, isc) & 255) << 16)
              | ((q8i((v[j].w - mu) * inv * w4.w + b4.w, isc) & 255) << 24);
        ((int*)outp)[lane + 32 * j] = p;
    }
}

// ------------------------------ merged prep kernel -------------------------
// blocks [0,2048): LN1; [2048,8960): weight quant; [8960,9060): pad fill.
#define QW_N0 442368
#define QW_N1 147456
#define QW_N2 589824
#define QW_TOT (QW_N0 + QW_N1 + QW_N2 + QW_N2)
#define PREP_LN   2048
#define PREP_QW   6912
#define PREP_GRID (PREP_LN + PREP_QW + NWIN)

__global__ void __launch_bounds__(256)
prep_kernel(const float* __restrict__ x, const float* __restrict__ lw,
            const float* __restrict__ lb,
            const float* __restrict__ w0, const float* __restrict__ w1,
            const float* __restrict__ w2, const float* __restrict__ w3,
            const float* __restrict__ ws, const float* __restrict__ qb,
            const float* __restrict__ as) {
    __shared__ int sq[192], sk[192];
    __shared__ int8_t sv[768];
    int blk = blockIdx.x, tid = threadIdx.x;

    if (blk < PREP_LN) {                       // ---- LN1 (pixel order) ----
        int lane = tid & 31, wid = tid >> 5;
        int m = blk * 8 + wid;
        ln_row(x + (size_t)m * DIMC, lw, lb, 1.0f / as[4],
               g_winq + (size_t)m * DIMC, lane);
        return;
    }
    if (blk < PREP_LN + PREP_QW) {             // ---- weight quant ----
        int i = (blk - PREP_LN) * 256 + tid;
        if (i >= QW_TOT) return;
        const float* src; int li; float inv; int8_t* dst;
        if (i < QW_N0)                      { src = w0; li = i;                         inv = 1.0f / ws[0]; dst = g_wqkv; }
        else if (i < QW_N0 + QW_N1)         { src = w1; li = i - QW_N0;                 inv = 1.0f / ws[1]; dst = g_wproj; }
        else if (i < QW_N0 + QW_N1 + QW_N2) { src = w2; li = i - QW_N0 - QW_N1;         inv = 1.0f / ws[2]; dst = g_wl1; }
        else                                { src = w3; li = i - QW_N0 - QW_N1 - QW_N2; inv = 1.0f / ws[3]; dst = g_wl2; }
        float4 v = ((const float4*)src)[li];
        int p = (q8i(v.x, inv) & 255) | ((q8i(v.y, inv) & 255) << 8) |
                ((q8i(v.z, inv) & 255) << 16) | ((q8i(v.w, inv) & 255) << 24);
        ((int*)dst)[li] = p;
        return;
    }
    // ---- pad-token q/k/vT fill (bias-only rows) ----
    int wi = blk - (PREP_LN + PREP_QW);
    int rem = wi % 25, wr = rem / 5, wc = rem % 5;
    if (wr < 4 && wc < 4) return;
    float inv0 = 1.0f / as[0], inv1 = 1.0f / as[1], inv2 = 1.0f / as[2];
    for (int i = tid; i < 192; i += 256) {
        int n = i * 4;
        sq[i] = (q8i(qb[n], inv0) & 255) | ((q8i(qb[n+1], inv0) & 255) << 8)
              | ((q8i(qb[n+2], inv0) & 255) << 16) | ((q8i(qb[n+3], inv0) & 255) << 24);
        sk[i] = (q8i(qb[768+n], inv1) & 255) | ((q8i(qb[768+n+1], inv1) & 255) << 8)
              | ((q8i(qb[768+n+2], inv1) & 255) << 16) | ((q8i(qb[768+n+3], inv1) & 255) << 24);
    }
    for (int i = tid; i < 768; i += 256) sv[i] = fq8m(qb[1536 + i], inv2);
    __syncthreads();
    int lane = tid & 31, w = tid >> 5;
    for (int t = w; t < NTOK; t += 8) {
        int lr = t / WSZ, lc = t % WSZ;
        bool pad = (wr == 4 && lr >= 8) || (wc == 4 && lc >= 8);
        if (!pad) continue;
        for (int i = lane; i < 192; i += 32) {
            int head = i >> 4, di = i & 15;
            ((int*)(g_q + ((size_t)(wi * NHEAD + head) * NTOK + t) * HDIM))[di] = sq[i];
            ((int*)(g_k + ((size_t)(wi * NHEAD + head) * NTOK + t) * HDIM))[di] = sk[i];
        }
        for (int i = lane; i < 768; i += 32) {
            int head = i >> 6, d = i & 63;
            g_vT[((size_t)(wi * NHEAD + head) * HDIM + d) * VPAD + t] = sv[i];
        }
    }
}

// ------------------------------ LN2 -----------------------------------------
__global__ void __launch_bounds__(256)
ln2_kernel(const float* __restrict__ lw, const float* __restrict__ lb,
           const float* __restrict__ as) {
    int lane = threadIdx.x & 31, wid = threadIdx.x >> 5;
    int m = blockIdx.x * 8 + wid;
    ln_row(g_xres + (size_t)m * DIMC, lw, lb, 1.0f / as[6], g_y + (size_t)m * DIMC, lane);
}

// ------------------------------ fused attention (+rel-pos bias) -------------
#define QSTR  20
#define SSTR  60
#define SQ_OFF   0
#define SK_OFF   (208 * QSTR)
#define SV_OFF   (SK_OFF + 200 * QSTR)
#define SS_OFF   (SV_OFF + 64 * SSTR)
#define RH_OFF   (SS_OFF + 208 * SSTR)
#define RW_OFF   (RH_OFF + 64 * 28)
#define REL_OFF  (RW_OFF + 64 * 28)
#define ATT_SMEM ((REL_OFF + 208 * 28) * 4)

__global__ void __launch_bounds__(416)
attn_fused_kernel(const float* __restrict__ rph, const float* __restrict__ rpw,
                  const float* __restrict__ as) {
    extern __shared__ int sm[];
    int* sQ = sm + SQ_OFF; int* sK = sm + SK_OFF;
    int* sVT = sm + SV_OFF; int* sS = sm + SS_OFF;
    float* sRhT = (float*)(sm + RH_OFF);
    float* sRwT = (float*)(sm + RW_OFF);
    float* sRel = (float*)(sm + REL_OFF);
    int bh = blockIdx.x, tid = threadIdx.x;
    int lane = tid & 31, wid = tid >> 5;
    int lrow = lane >> 2, lk = lane & 3;

    const int8_t* qg = g_q  + (size_t)bh * NTOK * HDIM;
    const int8_t* kg = g_k  + (size_t)bh * NTOK * HDIM;
    const int8_t* vg = g_vT + (size_t)bh * HDIM * VPAD;
    for (int idx = tid; idx < 208 * 4; idx += 416) {
        int row = idx >> 2, slot = idx & 3;
        int4 v = make_int4(0, 0, 0, 0);
        if (row < NTOK) v = *(const int4*)(qg + row * HDIM + slot * 16);
        *(int4*)&sQ[row * QSTR + slot * 4] = v;
    }
    for (int idx = tid; idx < 200 * 4; idx += 416) {
        int row = idx >> 2, slot = idx & 3;
        int4 v = make_int4(0, 0, 0, 0);
        if (row < NTOK) v = *(const int4*)(kg + row * HDIM + slot * 16);
        *(int4*)&sK[row * QSTR + slot * 4] = v;
    }
    for (int idx = tid; idx < 64 * 13; idx += 416) {
        int row = idx / 13, slot = idx % 13;
        *(int4*)&sVT[row * SSTR + slot * 4] = *(const int4*)(vg + row * VPAD + slot * 16);
    }
    for (int idx = tid; idx < 208 * 6; idx += 416)
        sS[(idx / 6) * SSTR + 50 + (idx % 6)] = 0;
    for (int i = tid; i < 27 * 64; i += 416) {
        int r = i >> 6, c = i & 63;
        sRhT[c * 28 + r] = rph[i];
        sRwT[c * 28 + r] = rpw[i];
    }
    __syncthreads();

    float a0s = as[0];
    if (tid < NTOK) {
        int t = tid;
        int hh = t / WSZ, ww2 = t % WSZ;
        float ah[WSZ], aw[WSZ];
#pragma unroll
        for (int kk = 0; kk < WSZ; ++kk) { ah[kk] = 0.f; aw[kk] = 0.f; }
#pragma unroll
        for (int j = 0; j < 16; ++j) {
            int packed = sQ[t * QSTR + j];
#pragma unroll
            for (int b = 0; b < 4; ++b) {
                int c = j * 4 + b;
                float qv = (float)((packed << (24 - 8 * b)) >> 24);
                const float* ph = &sRhT[c * 28 + hh + 13];
                const float* pw = &sRwT[c * 28 + ww2 + 13];
#pragma unroll
                for (int kk = 0; kk < WSZ; ++kk) {
                    ah[kk] += qv * ph[-kk];
                    aw[kk] += qv * pw[-kk];
                }
            }
        }
#pragma unroll
        for (int kk = 0; kk < WSZ; ++kk) {
            sRel[t * 28 + kk]      = ah[kk] * a0s;
            sRel[t * 28 + 14 + kk] = aw[kk] * a0s;
        }
    }
    __syncthreads();

    float c_qk = 0.125f * a0s * as[1];
    float inva3 = 1.0f / as[3];
    float c_av = as[3] * as[2];
    float inva5 = 1.0f / as[5];
    int wi = bh / NHEAD, head = bh % NHEAD;
    int wrem = wi % 25, wb = wi / 25, wwr = wrem / 5, wwc = wrem % 5;
    char* sSb = (char*)sS;

    {
        int s = wid;
        int m_lo = s * 16 + lrow, m_hi = m_lo + 8;
        int acc[25][4];
#pragma unroll
        for (int t = 0; t < 25; ++t) { acc[t][0]=acc[t][1]=acc[t][2]=acc[t][3]=0; }
#pragma unroll
        for (int kc = 0; kc < 2; ++kc) {
            int kb = kc * 8;
            int a0 = sQ[m_lo * QSTR + kb + lk];
            int a1 = sQ[m_hi * QSTR + kb + lk];
            int a2 = sQ[m_lo * QSTR + kb + 4 + lk];
            int a3 = sQ[m_hi * QSTR + kb + 4 + lk];
#pragma unroll
            for (int t = 0; t < 25; ++t) {
                int col = t * 8 + lrow;
                mma_s8(acc[t][0], acc[t][1], acc[t][2], acc[t][3],
                       a0, a1, a2, a3, sK[col * QSTR + kb + lk], sK[col * QSTR + kb + 4 + lk]);
            }
        }
        bool vlo = (m_lo < NTOK), vhi = (m_hi < NTOK);
        const float* rlo_p = &sRel[m_lo * 28];
        const float* rhi_p = &sRel[m_hi * 28];
#pragma unroll
        for (int t = 0; t < 25; ++t) {
#pragma unroll
            for (int r = 0; r < 4; ++r) {
                int n = t * 8 + lk * 2 + (r & 1);
                bool vm = (r < 2) ? vlo : vhi;
                float f;
                if (n < NTOK && vm) {
                    const float* rp = (r < 2) ? rlo_p : rhi_p;
                    f = (float)acc[t][r] * c_qk + rp[n / WSZ] + rp[14 + n % WSZ];
                } else f = -1e30f;
                acc[t][r] = __float_as_int(f);
            }
        }
        float mx0 = -1e30f, mx1 = -1e30f;
#pragma unroll
        for (int t = 0; t < 25; ++t) {
            mx0 = fmaxf(mx0, fmaxf(__int_as_float(acc[t][0]), __int_as_float(acc[t][1])));
            mx1 = fmaxf(mx1, fmaxf(__int_as_float(acc[t][2]), __int_as_float(acc[t][3])));
        }
        mx0 = fmaxf(mx0, __shfl_xor_sync(~0u, mx0, 1)); mx0 = fmaxf(mx0, __shfl_xor_sync(~0u, mx0, 2));
        mx1 = fmaxf(mx1, __shfl_xor_sync(~0u, mx1, 1)); mx1 = fmaxf(mx1, __shfl_xor_sync(~0u, mx1, 2));
        float s0 = 0.f, s1 = 0.f;
#pragma unroll
        for (int t = 0; t < 25; ++t) {
            float e0 = __expf(__int_as_float(acc[t][0]) - mx0);
            float e1 = __expf(__int_as_float(acc[t][1]) - mx0);
            float e2 = __expf(__int_as_float(acc[t][2]) - mx1);
            float e3 = __expf(__int_as_float(acc[t][3]) - mx1);
            acc[t][0] = __float_as_int(e0); acc[t][1] = __float_as_int(e1);
            acc[t][2] = __float_as_int(e2); acc[t][3] = __float_as_int(e3);
            s0 += e0 + e1; s1 += e2 + e3;
        }
        s0 += __shfl_xor_sync(~0u, s0, 1); s0 += __shfl_xor_sync(~0u, s0, 2);
        s1 += __shfl_xor_sync(~0u, s1, 1); s1 += __shfl_xor_sync(~0u, s1, 2);
        float r0 = inva3 / s0, r1 = inva3 / s1;
#pragma unroll
        for (int t = 0; t < 25; ++t) {
            int v00 = q8i(__int_as_float(acc[t][0]), r0);
            int v01 = q8i(__int_as_float(acc[t][1]), r0);
            int v10 = q8i(__int_as_float(acc[t][2]), r1);
            int v11 = q8i(__int_as_float(acc[t][3]), r1);
            *(unsigned short*)(sSb + m_lo * (SSTR * 4) + t * 8 + lk * 2) =
                (unsigned short)((v00 & 0xFF) | ((v01 & 0xFF) << 8));
            *(unsigned short*)(sSb + m_hi * (SSTR * 4) + t * 8 + lk * 2) =
                (unsigned short)((v10 & 0xFF) | ((v11 & 0xFF) << 8));
        }
        __syncwarp();
        int oacc[8][4];
#pragma unroll
        for (int j = 0; j < 8; ++j) { oacc[j][0]=oacc[j][1]=oacc[j][2]=oacc[j][3]=0; }
#pragma unroll
        for (int kc = 0; kc < 7; ++kc) {
            int kb = kc * 8;
            int a0 = sS[m_lo * SSTR + kb + lk];
            int a1 = sS[m_hi * SSTR + kb + lk];
            int a2 = sS[m_lo * SSTR + kb + 4 + lk];
            int a3 = sS[m_hi * SSTR + kb + 4 + lk];
#pragma unroll
            for (int j = 0; j < 8; ++j) {
                int col = j * 8 + lrow;
                mma_s8(oacc[j][0], oacc[j][1], oacc[j][2], oacc[j][3],
                       a0, a1, a2, a3, sVT[col * SSTR + kb + lk], sVT[col * SSTR + kb + 4 + lk]);
            }
        }
        int rlo = wwr * WSZ + m_lo / WSZ, clo = wwc * WSZ + m_lo % WSZ;
        int rhi = wwr * WSZ + m_hi / WSZ, chi = wwc * WSZ + m_hi % WSZ;
        bool oklo = vlo && rlo < HH && clo < WW;
        bool okhi = vhi && rhi < HH && chi < WW;
        size_t plo = (((size_t)(wb * HH + rlo)) * WW + clo) * DIMC + head * HDIM;
        size_t phi = (((size_t)(wb * HH + rhi)) * WW + chi) * DIMC + head * HDIM;
#pragma unroll
        for (int j = 0; j < 8; ++j) {
            int n = j * 8 + lk * 2;
            if (oklo) {
                int v0 = q8i((float)oacc[j][0] * c_av, inva5);
                int v1 = q8i((float)oacc[j][1] * c_av, inva5);
                *(unsigned short*)(g_ov + plo + n) =
                    (unsigned short)((v0 & 0xFF) | ((v1 & 0xFF) << 8));
            }
            if (okhi) {
                int v0 = q8i((float)oacc[j][2] * c_av, inva5);
                int v1 = q8i((float)oacc[j][3] * c_av, inva5);
                *(unsigned short*)(g_ov + phi + n) =
                    (unsigned short)((v0 & 0xFF) | ((v1 & 0xFF) << 8));
            }
        }
    }
}

// ------------------------------ int8 IMMA GEMM (cp.async + ldmatrix) --------
// Templated on NJ = n8-tiles per warp (4 -> 128x128 CTA tile, 2 -> 128x64).
// Stage layout: [stage][A 10240B | B 2560*NJ B]; 3 stages; wait_group 1.
template <int NJ>
struct GemmSmem { static constexpr int STG = 10240 + 2560 * NJ;
                  static constexpr int TOT = 3 * STG; };

template <int NJ, typename Epi>
__global__ void __launch_bounds__(256)
gemm_i8(int aid, int bid, int Kints, Epi epi) {
    extern __shared__ int gsm[];
    constexpr int STG = GemmSmem<NJ>::STG;
    const int8_t* Ab = srcA(aid);
    const int8_t* Bb = srcB(bid);
    int bm = blockIdx.y * 128, bn = blockIdx.x * (32 * NJ);
    int tid = threadIdx.x;
    int lane = tid & 31, wid = tid >> 5;
    int wm = wid >> 2, wn = wid & 3;
    int lrow = lane >> 2, lk = lane & 3;
    int srow = tid >> 2;
    int slot = tid & 3;

    uint32_t sbase = (uint32_t)__cvta_generic_to_shared(gsm);
    const int* Abase = (const int*)Ab + (size_t)(bm + srow) * Kints + slot * 4;
    const int* Bbase = (const int*)Bb + (size_t)(bn + srow) * Kints + slot * 4;
    size_t rowskip = (size_t)64 * Kints;
    uint32_t a_off = sbase + srow * 80 + slot * 16;
    uint32_t b_off = sbase + 10240 + srow * 80 + slot * 16;

    uint32_t aLm = sbase + (wm * 64 + (lane & 15)) * 80 + ((lane >> 4) << 4);
    uint32_t bLm = sbase + 10240 +
                   (wn * (8 * NJ) + ((lane >> 4) << 3) + (lane & 7)) * 80 +
                   (((lane >> 3) & 1) << 4);

    int acc[4][NJ][4];
#pragma unroll
    for (int i = 0; i < 4; ++i)
#pragma unroll
        for (int j = 0; j < NJ; ++j)
#pragma unroll
            for (int r = 0; r < 4; ++r) acc[i][j][r] = 0;

    auto load_tile = [&](int kt, int stg) {
        int k0 = kt * 16;
        const int* ga = Abase + k0;
        const int* gb = Bbase + k0;
        uint32_t ao = a_off + stg * STG;
        uint32_t bo = b_off + stg * STG;
        CP_ASYNC16(ao, ga);
        CP_ASYNC16(ao + 64 * 80, ga + rowskip);
#pragma unroll
        for (int rr = 0; rr < NJ / 2; ++rr)
            CP_ASYNC16(bo + rr * 64 * 80, gb + rr * rowskip);
        CP_COMMIT();
    };

    int nk = Kints >> 4;
    load_tile(0, 0);
    load_tile(1, 1);

    for (int kt = 0; kt < nk; ++kt) {
        CP_WAIT1();
        __syncthreads();
        int cur = kt - (kt / 3) * 3;
        uint32_t aC = aLm + cur * STG;
        uint32_t bC = bLm + cur * STG;
#pragma unroll
        for (int kc = 0; kc < 2; ++kc) {
            uint32_t koff = kc * 32;
            int b0[NJ], b1[NJ];
#pragma unroll
            for (int jp = 0; jp < NJ / 2; ++jp)
                ldsm_x4(b0[2 * jp], b1[2 * jp], b0[2 * jp + 1], b1[2 * jp + 1],
                        bC + jp * 1280 + koff);
#pragma unroll
            for (int i = 0; i < 4; ++i) {
                int a0, a1, a2, a3;
                ldsm_x4(a0, a1, a2, a3, aC + i * 1280 + koff);
#pragma unroll
                for (int j = 0; j < NJ; ++j)
                    mma_s8(acc[i][j][0], acc[i][j][1], acc[i][j][2], acc[i][j][3],
                           a0, a1, a2, a3, b0[j], b1[j]);
            }
        }
        if (kt + 2 < nk) {
            int stg = kt + 2;
            stg -= (stg / 3) * 3;
            load_tile(kt + 2, stg);
        }
    }

    epi.prep();
#pragma unroll
    for (int i = 0; i < 4; ++i) {
        int m0 = bm + wm * 64 + i * 16 + lrow;
#pragma unroll
        for (int j = 0; j < NJ; ++j) {
            int n0 = bn + wn * (8 * NJ) + j * 8 + lk * 2;
            epi.pair(acc[i][j][0], acc[i][j][1], m0, n0);
            epi.pair(acc[i][j][2], acc[i][j][3], m0 + 8, n0);
        }
    }
}

// ------------------------------ GEMM epilogues (paired, n even) -------------
struct EpiQKV {
    const float* as; const float* ws; const float* qb;
    float s1, inv0, inv1, inv2;
    __device__ void prep() {
        s1 = as[4] * ws[0];
        inv0 = 1.0f / as[0]; inv1 = 1.0f / as[1]; inv2 = 1.0f / as[2];
    }
    __device__ void pair(int acc0, int acc1, int m, int n) const {
        float f0 = (float)acc0 * s1 + qb[n];
        float f1 = (float)acc1 * s1 + qb[n + 1];
        int qi = (n >= 1536) ? 2 : (n >= 768 ? 1 : 0);
        int rem = n - qi * 768;
        int head = rem >> 6, d = rem & 63;
        int b = m >> 12, r = (m >> 6) & 63, c = m & 63;
        int wr = r / WSZ, lr = r - wr * WSZ;
        int wc = c / WSZ, lc = c - wc * WSZ;
        int wi = b * 25 + wr * 5 + wc;
        int t = lr * WSZ + lc;
        int bh = wi * NHEAD + head;
        if (qi == 0) {
            int v0 = q8i(f0, inv0), v1 = q8i(f1, inv0);
            *(unsigned short*)(g_q + ((size_t)bh * NTOK + t) * HDIM + d) =
                (unsigned short)((v0 & 0xFF) | ((v1 & 0xFF) << 8));
        } else if (qi == 1) {
            int v0 = q8i(f0, inv1), v1 = q8i(f1, inv1);
            *(unsigned short*)(g_k + ((size_t)bh * NTOK + t) * HDIM + d) =
                (unsigned short)((v0 & 0xFF) | ((v1 & 0xFF) << 8));
        } else {
            g_vT[((size_t)bh * HDIM + d)     * VPAD + t] = fq8m(f0, inv2);
            g_vT[((size_t)bh * HDIM + d + 1) * VPAD + t] = fq8m(f1, inv2);
        }
    }
};
struct EpiProj {
    const float* as; const float* ws; const float* pb; const float* x;
    float s1;
    __device__ void prep() { s1 = as[5] * ws[1]; }
    __device__ void pair(int acc0, int acc1, int m, int n) const {
        size_t idx = (size_t)m * DIMC + n;
        float2 xv = *(const float2*)(x + idx);
        float2 o;
        o.x = xv.x + (float)acc0 * s1 + pb[n];
        o.y = xv.y + (float)acc1 * s1 + pb[n + 1];
        *(float2*)(g_xres + idx) = o;
    }
};
struct EpiL1 {
    const float* as; const float* ws; const float* lb;
    float s1, inv7;
    __device__ void prep() { s1 = as[6] * ws[2]; inv7 = 1.0f / as[7]; }
    __device__ float gelu(float f) const {
        float xx = f * 0.70710678118654752f;
        float ax = fabsf(xx);
        float t = __fdividef(1.0f, 1.0f + 0.3275911f * ax);
        float poly = t * (0.254829592f + t * (-0.284496736f + t * (1.421413741f +
                     t * (-1.453152027f + t * 1.061405429f))));
        float erfv = 1.0f - poly * __expf(-xx * xx);
        erfv = copysignf(erfv, xx);
        return 0.5f * f * (1.0f + erfv);
    }
    __device__ void pair(int acc0, int acc1, int m, int n) const {
        float f0 = (float)acc0 * s1 + lb[n];
        float f1 = (float)acc1 * s1 + lb[n + 1];
        int v0 = q8i(gelu(f0), inv7);
        int v1 = q8i(gelu(f1), inv7);
        *(unsigned short*)(g_hbuf + (size_t)m * MLPD + n) =
            (unsigned short)((v0 & 0xFF) | ((v1 & 0xFF) << 8));
    }
};
struct EpiL2 {
    const float* as; const float* ws; const float* lb; float* out;
    float s1;
    __device__ void prep() { s1 = as[7] * ws[3]; }
    __device__ void pair(int acc0, int acc1, int m, int n) const {
        size_t idx = (size_t)m * DIMC + n;
        float2 rv = *(const float2*)(g_xres + idx);
        float2 o;
        o.x = rv.x + (float)acc0 * s1 + lb[n];
        o.y = rv.y + (float)acc1 * s1 + lb[n + 1];
        *(float2*)(out + idx) = o;
    }
};

// ------------------------------ launch --------------------------------------
extern "C" void kernel_launch(void* const* d_in, const int* in_sizes, int n_in,
                              void* d_out, int out_size) {
    const float* x      = (const float*)d_in[0];
    const float* ln1_w  = (const float*)d_in[1];
    const float* ln1_b  = (const float*)d_in[2];
    const float* ln2_w  = (const float*)d_in[3];
    const float* ln2_b  = (const float*)d_in[4];
    const float* qkv_w  = (const float*)d_in[5];
    const float* qkv_b  = (const float*)d_in[6];
    const float* proj_w = (const float*)d_in[7];
    const float* proj_b = (const float*)d_in[8];
    const float* lin1_w = (const float*)d_in[9];
    const float* lin1_b = (const float*)d_in[10];
    const float* lin2_w = (const float*)d_in[11];
    const float* lin2_b = (const float*)d_in[12];
    const float* rph    = (const float*)d_in[13];
    const float* rpw    = (const float*)d_in[14];
    const float* asc    = (const float*)d_in[15];
    const float* wsc    = (const float*)d_in[16];
    float* out = (float*)d_out;

    cudaFuncSetAttribute(attn_fused_kernel, cudaFuncAttributeMaxDynamicSharedMemorySize, ATT_SMEM);
    cudaFuncSetAttribute(gemm_i8<4, EpiQKV>, cudaFuncAttributeMaxDynamicSharedMemorySize, GemmSmem<4>::TOT);
    cudaFuncSetAttribute(gemm_i8<2, EpiProj>, cudaFuncAttributeMaxDynamicSharedMemorySize, GemmSmem<2>::TOT);
    cudaFuncSetAttribute(gemm_i8<4, EpiL1>,  cudaFuncAttributeMaxDynamicSharedMemorySize, GemmSmem<4>::TOT);
    cudaFuncSetAttribute(gemm_i8<2, EpiL2>,  cudaFuncAttributeMaxDynamicSharedMemorySize, GemmSmem<2>::TOT);

    // 1) LN1 + weight quant + pad fill in ONE heterogeneous launch
    prep_kernel<<<PREP_GRID, 256>>>(x, ln1_w, ln1_b,
                                    qkv_w, proj_w, lin1_w, lin2_w,
                                    wsc, qkv_b, asc);

    // 2) QKV GEMM (128x128 tiles)
    gemm_i8<4, EpiQKV><<<dim3(18, 128), 256, GemmSmem<4>::TOT>>>(0, 0, DIMC / 4,
                                                                 EpiQKV{asc, wsc, qkv_b});

    // 3) fused attention (rel-pos in-kernel)
    attn_fused_kernel<<<BHD, 416, ATT_SMEM>>>(rph, rpw, asc);

    // 4) proj GEMM (128x64 tiles -> better wave quantization) + residual
    gemm_i8<2, EpiProj><<<dim3(12, 128), 256, GemmSmem<2>::TOT>>>(3, 3, DIMC / 4,
                                                                  EpiProj{asc, wsc, proj_b, x});

    // 5) LN2
    ln2_kernel<<<PIX / 8, 256>>>(ln2_w, ln2_b, asc);

    // 6) MLP
    gemm_i8<4, EpiL1><<<dim3(24, 128), 256, GemmSmem<4>::TOT>>>(4, 4, DIMC / 4,
                                                                EpiL1{asc, wsc, lin1_b});
    gemm_i8<2, EpiL2><<<dim3(12, 128), 256, GemmSmem<2>::TOT>>>(5, 5, MLPD / 4,
                                                                EpiL2{asc, wsc, lin2_b, out});
}